// round 12
// baseline (speedup 1.0000x reference)
#include <cuda_runtime.h>
#include <cstdint>

#define NN 50000
#define NE 800000

// ---------------- device scratch ----------------
__device__ float g_AB[NN * 512];      // [n][0:256)=h@We1a^T, [256:512)=h@We1b^T
__device__ float g_agg[NN * 256];
__device__ float g_csum[NN * 3];
__device__ float g_cnt[NN];
__device__ float g_wr[256];
// fragment-ordered tf32 weights, B-fragment of mma.m16n8k8:
//   index = ((kb*4 + k8)*NS + n8)*64 + lane*2 + i
//   holds B[k][n], k = kb*32 + k8*8 + (lane&3) + 4*i, n = n8*8 + (lane>>2)
__device__ float g_W2F[256 * 256];    // NS=32
__device__ float g_Wc1F[256 * 256];   // NS=32
__device__ float g_W1F[256 * 512];    // NS=64 (n = 0..511 over [We1a|We1b])
__device__ float g_Wn1F[512 * 256];   // NS=32, kb=0..15 (K=512)
__device__ float g_Wn2F[256 * 256];   // NS=32

__device__ __forceinline__ float silu_f(float v) {
    return __fdividef(v, 1.0f + __expf(-v));
}
__device__ __forceinline__ uint32_t tf32_rna(float v) {
    uint32_t r;
    asm("cvt.rna.tf32.f32 %0, %1;" : "=r"(r) : "f"(v));
    return r;
}
__device__ __forceinline__ void mma_tf32(float d[4], uint32_t a0, uint32_t a1,
                                         uint32_t a2, uint32_t a3,
                                         uint32_t b0, uint32_t b1) {
    asm volatile(
        "mma.sync.aligned.m16n8k8.row.col.f32.tf32.tf32.f32 "
        "{%0,%1,%2,%3},{%4,%5,%6,%7},{%8,%9},{%0,%1,%2,%3};"
        : "+f"(d[0]), "+f"(d[1]), "+f"(d[2]), "+f"(d[3])
        : "r"(a0), "r"(a1), "r"(a2), "r"(a3), "r"(b0), "r"(b1));
}
__device__ __forceinline__ void red_add_v4(float* p, float a, float b, float c, float e) {
    asm volatile("red.global.add.v4.f32 [%0], {%1,%2,%3,%4};"
                 :: "l"(p), "f"(a), "f"(b), "f"(c), "f"(e) : "memory");
}
__device__ __forceinline__ void cp_async8(uint32_t saddr, const float* gptr) {
    asm volatile("cp.async.ca.shared.global [%0], [%1], 8;"
                 :: "r"(saddr), "l"(gptr) : "memory");
}
#define CP_COMMIT() asm volatile("cp.async.commit_group;" ::: "memory")
#define CP_WAIT3()  asm volatile("cp.async.wait_group 3;" ::: "memory")

// ---------------- prep: fragment-order weights, zero accumulators ----------------
__global__ void prep_kernel(const float* __restrict__ We1,
                            const float* __restrict__ We2,
                            const float* __restrict__ Wc1,
                            const float* __restrict__ Wn1,
                            const float* __restrict__ Wn2) {
    int i = blockIdx.x * blockDim.x + threadIdx.x;
    int stride = gridDim.x * blockDim.x;
    for (int t = i; t < NN * 256; t += stride) g_agg[t] = 0.0f;
    for (int t = i; t < NN * 3; t += stride) g_csum[t] = 0.0f;
    for (int t = i; t < NN; t += stride) g_cnt[t] = 0.0f;
    for (int t = i; t < 256; t += stride) g_wr[t] = We1[t * 513 + 512];
    // NS=32 fragment tables (256x256)
    for (int t = i; t < 65536; t += stride) {
        int ii = t & 1;
        int lanei = (t >> 1) & 31;
        int n8 = (t >> 6) & 31;
        int k8 = (t >> 11) & 3;
        int kb = t >> 13;
        int k = kb * 32 + k8 * 8 + (lanei & 3) + 4 * ii;
        int o = n8 * 8 + (lanei >> 2);
        g_W2F[t]  = __uint_as_float(tf32_rna(We2[o * 256 + k]));
        g_Wc1F[t] = __uint_as_float(tf32_rna(Wc1[o * 256 + k]));
        g_Wn2F[t] = __uint_as_float(tf32_rna(Wn2[o * 256 + k]));
    }
    // g_W1F: NS=64, K=256, n=0..511 over [We1a | We1b]
    for (int t = i; t < 131072; t += stride) {
        int ii = t & 1;
        int lanei = (t >> 1) & 31;
        int n8 = (t >> 6) & 63;
        int k8 = (t >> 12) & 3;
        int kb = t >> 14;
        int k = kb * 32 + k8 * 8 + (lanei & 3) + 4 * ii;
        int j = n8 * 8 + (lanei >> 2);
        float v = (j < 256) ? We1[j * 513 + k] : We1[(j - 256) * 513 + 256 + k];
        g_W1F[t] = __uint_as_float(tf32_rna(v));
    }
    // g_Wn1F: NS=32, K=512 (kb = 0..15)
    for (int t = i; t < 131072; t += stride) {
        int ii = t & 1;
        int lanei = (t >> 1) & 31;
        int n8 = (t >> 6) & 31;
        int k8 = (t >> 11) & 3;
        int kb = t >> 13;
        int k = kb * 32 + k8 * 8 + (lanei & 3) + 4 * ii;
        int o = n8 * 8 + (lanei >> 2);
        g_Wn1F[t] = __uint_as_float(tf32_rna(Wn1[o * 512 + k]));
    }
}

// ---------------- shared mma building blocks ----------------
// 64 x 32 x 256-chunk per-warp tf32 GEMM accumulate. Warp covers ALL 64 rows
// (4 A frags from SMEM) x 32 cols. B streamed via cp.async into a per-warp
// private 5-slot SMEM ring at prefetch distance 4 (wait_group 3). A slot is
// rewritten one full iteration after its LDS -> no same-slot WAR hazard.
// a_s: A fragments [ks(32)][mt(4)][lane(32)][4]. No barriers inside.
// ring_s: shared-space byte address of THIS warp's ring + lane*8.
//   frag (slot, nt) element for this lane at ring_s + (slot*4 + nt)*256.
// RING floats per warp = 5*4*32*2 = 1280; per 8-warp CTA = 10240.
#define RING_FLOATS_CTA 10240

template <int NS>
__device__ __forceinline__ void mma_gemm_cp(
    const float* a_s, uint32_t ring_s, const float* __restrict__ WF,
    int n8base, int kb0, float d[4][4][4], int lane) {
    const float* bb = WF + ((size_t)(kb0 * 4 * NS + n8base)) * 64 + lane * 2;
    const size_t kstride = (size_t)NS * 64;
    // prologue: stages for ks = 0..3 into slots 0..3
#pragma unroll
    for (int s = 0; s < 4; s++) {
        const float* src = bb + (size_t)s * kstride;
#pragma unroll
        for (int nt = 0; nt < 4; nt++)
            cp_async8(ring_s + (s * 4 + nt) * 256, src + (size_t)nt * 64);
        CP_COMMIT();
    }
    for (int ks = 0; ks < 32; ks++) {
        CP_WAIT3();                       // slot (ks%5) data has landed
        int slot = ks % 5;
        uint2 Bc[4];
#pragma unroll
        for (int nt = 0; nt < 4; nt++)
            asm volatile("ld.shared.v2.u32 {%0,%1}, [%2];"
                         : "=r"(Bc[nt].x), "=r"(Bc[nt].y)
                         : "r"(ring_s + (slot * 4 + nt) * 256));
        int ksn = ks + 4;
        if (ksn < 32) {                   // refill slot (ks+4)%5 = slot read LAST iter
            int slotn = ksn % 5;
            const float* src = bb + (size_t)ksn * kstride;
#pragma unroll
            for (int nt = 0; nt < 4; nt++)
                cp_async8(ring_s + (slotn * 4 + nt) * 256, src + (size_t)nt * 64);
        }
        CP_COMMIT();                      // commit (possibly empty) to keep counts aligned
        uint4 A[4];
#pragma unroll
        for (int mt = 0; mt < 4; mt++)
            A[mt] = *(const uint4*)&a_s[((ks * 4 + mt) * 32 + lane) * 4];
#pragma unroll
        for (int nt = 0; nt < 4; nt++)
#pragma unroll
            for (int mt = 0; mt < 4; mt++)
                mma_tf32(d[mt][nt], A[mt].x, A[mt].y, A[mt].z, A[mt].w,
                         Bc[nt].x, Bc[nt].y);
    }
}

__device__ __forceinline__ void zero_d(float d[4][4][4]) {
#pragma unroll
    for (int mt = 0; mt < 4; mt++)
#pragma unroll
        for (int nt = 0; nt < 4; nt++)
#pragma unroll
            for (int q = 0; q < 4; q++) d[mt][nt][q] = 0.0f;
}

// Build A fragments (rounded to tf32) for a 256-col row-major source.
__device__ __forceinline__ void build_a_frags(float* a_s, const float* src,
                                              int e, int jq) {
    int mt = e >> 4, hi = (e >> 3) & 1, lb = (e & 7) * 4;
#pragma unroll
    for (int jb = 0; jb < 16; jb++) {
        int j = jb * 16 + jq * 4;
        float4 x = *(const float4*)&src[j];
        int ks = j >> 3, chi = (j >> 2) & 1;
        int base = ((ks * 4 + mt) * 32 + lb) * 4 + hi + 2 * chi;
        a_s[base + 0]  = __uint_as_float(tf32_rna(x.x));
        a_s[base + 4]  = __uint_as_float(tf32_rna(x.y));
        a_s[base + 8]  = __uint_as_float(tf32_rna(x.z));
        a_s[base + 12] = __uint_as_float(tf32_rna(x.w));
    }
}

// a_s fragment index for (row e, col) in MT=4 layout
__device__ __forceinline__ int afrag_idx(int e, int col) {
    int cc = col & 7, tg = cc & 3, chi2 = cc >> 2;
    return (((col >> 3) * 4 + (e >> 4)) * 32 + (e & 7) * 4 + tg) * 4
         + ((e >> 3) & 1) + 2 * chi2;
}

// per-warp ring shared address (byte), from CTA ring base (float*)
__device__ __forceinline__ uint32_t ring_addr(const float* ring_base, int wid, int lane) {
    return (uint32_t)__cvta_generic_to_shared(ring_base) + wid * 5120 + lane * 8;
}

// ---------------- K1: AB = h @ [We1a^T | We1b^T]  (tf32 mma) ----------------
#define AB_SMEM_FLOATS (16384 + RING_FLOATS_CTA)
#define AB_SMEM_BYTES  (AB_SMEM_FLOATS * 4)

__global__ __launch_bounds__(256, 2) void gemm_ab(const float* __restrict__ h) {
    extern __shared__ float sm[];
    float* a_s  = sm;            // 16384
    float* ring = a_s + 16384;   // 10240

    int tid = threadIdx.x;
    int lane = tid & 31, wid = tid >> 5;
    int gid = lane >> 2, tig = lane & 3;
    int row0 = blockIdx.x * 64;
    int jbase = blockIdx.y * 256;
    uint32_t ring_s = ring_addr(ring, wid, lane);

    {
        int e = tid >> 2, jq = tid & 3;
        int row = row0 + e; if (row >= NN) row = NN - 1;
        build_a_frags(a_s, &h[row * 256], e, jq);
    }
    __syncthreads();

    float d[4][4][4];
    zero_d(d);
    mma_gemm_cp<64>(a_s, ring_s, g_W1F, blockIdx.y * 32 + wid * 4, 0, d, lane);

#pragma unroll
    for (int mt = 0; mt < 4; mt++) {
        int row = row0 + mt * 16 + gid;
#pragma unroll
        for (int nt = 0; nt < 4; nt++) {
            int col = jbase + wid * 32 + nt * 8 + 2 * tig;
            if (row < NN)
                *(float2*)&g_AB[row * 512 + col] =
                    make_float2(d[mt][nt][0], d[mt][nt][1]);
            if (row + 8 < NN)
                *(float2*)&g_AB[(row + 8) * 512 + col] =
                    make_float2(d[mt][nt][2], d[mt][nt][3]);
        }
    }
}

// ---------------- edge kernel: 64 edges/CTA, 256 threads ----------------
#define EDGE_SMEM_FLOATS (16384 + RING_FLOATS_CTA + 5*256 + 64 + 192 + 64 + 128)
#define EDGE_SMEM_BYTES  (EDGE_SMEM_FLOATS * 4)

__global__ __launch_bounds__(256, 2) void edge_kernel(
    const int* __restrict__ eidx, const float* __restrict__ coord,
    const float* __restrict__ be1, const float* __restrict__ be2,
    const float* __restrict__ bc1, const float* __restrict__ Wc2) {
    extern __shared__ float sm[];
    float* a_s   = sm;                       // 16384
    float* ring  = a_s + 16384;              // 10240
    float* wr_s  = ring + RING_FLOATS_CTA;
    float* be1_s = wr_s + 256;
    float* be2_s = be1_s + 256;
    float* bc1_s = be2_s + 256;
    float* wc2_s = bc1_s + 256;
    float* rad_s = wc2_s + 256;              // 64
    float* diff_s = rad_s + 64;              // 192
    float* psum_s = diff_s + 192;            // 64
    int*   rows_s = (int*)(psum_s + 64);     // 64
    int*   cols_s = rows_s + 64;             // 64

    int tid = threadIdx.x;
    int lane = tid & 31, wid = tid >> 5;
    int gid = lane >> 2, tig = lane & 3;
    int e0 = blockIdx.x * 64;
    uint32_t ring_s = ring_addr(ring, wid, lane);

    wr_s[tid]  = g_wr[tid];
    be1_s[tid] = be1[tid];
    be2_s[tid] = be2[tid];
    bc1_s[tid] = bc1[tid];
    wc2_s[tid] = Wc2[tid];
    if (tid < 64) {
        psum_s[tid] = 0.0f;
        int r = eidx[e0 + tid], c = eidx[NE + e0 + tid];
        rows_s[tid] = r; cols_s[tid] = c;
        float dx = coord[r * 3]     - coord[c * 3];
        float dy = coord[r * 3 + 1] - coord[c * 3 + 1];
        float dz = coord[r * 3 + 2] - coord[c * 3 + 2];
        diff_s[tid * 3]     = dx;
        diff_s[tid * 3 + 1] = dy;
        diff_s[tid * 3 + 2] = dz;
        rad_s[tid] = dx * dx + dy * dy + dz * dz;
    }
    __syncthreads();

    // ---- stage 1: m = silu(A[row]+B[col]+rad*wr+be1), A-fragment layout (rna) ----
    {
        int e = tid >> 2, jq = tid & 3;
        int rrow = rows_s[e], ccol = cols_s[e];
        float rad = rad_s[e];
        const float* ap = &g_AB[rrow * 512];
        const float* bp = &g_AB[ccol * 512 + 256];
        int mt = e >> 4, hi = (e >> 3) & 1, lb = (e & 7) * 4;
#pragma unroll
        for (int jb = 0; jb < 16; jb++) {
            int j = jb * 16 + jq * 4;
            float4 a  = *(const float4*)&ap[j];
            float4 b  = *(const float4*)&bp[j];
            float4 w  = *(const float4*)&wr_s[j];
            float4 bb = *(const float4*)&be1_s[j];
            float mv[4];
            mv[0] = silu_f(a.x + b.x + rad * w.x + bb.x);
            mv[1] = silu_f(a.y + b.y + rad * w.y + bb.y);
            mv[2] = silu_f(a.z + b.z + rad * w.z + bb.z);
            mv[3] = silu_f(a.w + b.w + rad * w.w + bb.w);
            int ks = j >> 3, chi = (j >> 2) & 1;
            int base = ((ks * 4 + mt) * 32 + lb) * 4 + hi + 2 * chi;
#pragma unroll
            for (int q = 0; q < 4; q++)
                a_s[base + q * 4] = __uint_as_float(tf32_rna(mv[q]));
        }
    }
    __syncthreads();

    float d[4][4][4];

    // ---- stage 2: ef = silu(m @ We2^T + be2) ----
    zero_d(d);
    mma_gemm_cp<32>(a_s, ring_s, g_W2F, wid * 4, 0, d, lane);
    __syncthreads();   // all warps done reading m before a_s is overwritten
#pragma unroll
    for (int mt = 0; mt < 4; mt++) {
        int e_lo = mt * 16 + gid;
#pragma unroll
        for (int nt = 0; nt < 4; nt++) {
            int colb = wid * 32 + nt * 8 + 2 * tig;
#pragma unroll
            for (int q = 0; q < 4; q++) {
                int e = e_lo + (q >> 1) * 8;
                int col = colb + (q & 1);
                float v = silu_f(d[mt][nt][q] + be2_s[col]);
                a_s[afrag_idx(e, col)] = v;  // raw f32; mma truncates later
            }
        }
    }
    __syncthreads();   // publish ef

    // ---- agg scatter: 4 cols per vector RED ----
    {
        int e = tid >> 2, cg = tid & 3;
        int r = rows_s[e];
        int mt = e >> 4, hi8 = (e >> 3) & 1, lb = (e & 7) * 4;
#pragma unroll
        for (int b = 0; b < 16; b++) {
            int col = cg * 64 + b * 4;
            int ks = col >> 3, chi2 = (col >> 2) & 1;
            int base = ((ks * 4 + mt) * 32 + lb) * 4 + hi8 + 2 * chi2;
            red_add_v4(&g_agg[r * 256 + col],
                       a_s[base], a_s[base + 4], a_s[base + 8], a_s[base + 12]);
        }
    }

    // ---- stage 3: phi = silu(ef @ Wc1^T + bc1) . Wc2 ; coord scatter ----
    zero_d(d);
    mma_gemm_cp<32>(a_s, ring_s, g_Wc1F, wid * 4, 0, d, lane);
    float s[4][2];
#pragma unroll
    for (int mt = 0; mt < 4; mt++) { s[mt][0] = 0.0f; s[mt][1] = 0.0f; }
#pragma unroll
    for (int mt = 0; mt < 4; mt++)
#pragma unroll
        for (int nt = 0; nt < 4; nt++) {
            int colb = wid * 32 + nt * 8 + 2 * tig;
            float w0 = wc2_s[colb], w1 = wc2_s[colb + 1];
            float b0 = bc1_s[colb], b1 = bc1_s[colb + 1];
            s[mt][0] += silu_f(d[mt][nt][0] + b0) * w0 + silu_f(d[mt][nt][1] + b1) * w1;
            s[mt][1] += silu_f(d[mt][nt][2] + b0) * w0 + silu_f(d[mt][nt][3] + b1) * w1;
        }
#pragma unroll
    for (int off = 1; off <= 2; off <<= 1)
#pragma unroll
        for (int mt = 0; mt < 4; mt++) {
            s[mt][0] += __shfl_xor_sync(0xffffffffu, s[mt][0], off);
            s[mt][1] += __shfl_xor_sync(0xffffffffu, s[mt][1], off);
        }
    if (tig == 0) {
#pragma unroll
        for (int mt = 0; mt < 4; mt++) {
            atomicAdd(&psum_s[mt * 16 + gid],     s[mt][0]);
            atomicAdd(&psum_s[mt * 16 + 8 + gid], s[mt][1]);
        }
    }
    __syncthreads();
    if (tid < 64) {
        float phi = psum_s[tid];
        int r = rows_s[tid];
        atomicAdd(&g_csum[r * 3],     diff_s[tid * 3]     * phi);
        atomicAdd(&g_csum[r * 3 + 1], diff_s[tid * 3 + 1] * phi);
        atomicAdd(&g_csum[r * 3 + 2], diff_s[tid * 3 + 2] * phi);
        atomicAdd(&g_cnt[r], 1.0f);
    }
}

// ---------------- node MLP + residual (tf32 mma) ----------------
#define NODE_SMEM_FLOATS (16384 + RING_FLOATS_CTA + 512)
#define NODE_SMEM_BYTES  (NODE_SMEM_FLOATS * 4)

__global__ __launch_bounds__(256, 2) void node_kernel(
    const float* __restrict__ h, const float* __restrict__ bn1,
    const float* __restrict__ bn2, float* __restrict__ out) {
    extern __shared__ float sm[];
    float* a_s   = sm;                        // 16384
    float* ring  = a_s + 16384;               // 10240
    float* bn1_s = ring + RING_FLOATS_CTA;    // 256
    float* bn2_s = bn1_s + 256;               // 256

    int tid = threadIdx.x;
    int lane = tid & 31, wid = tid >> 5;
    int gid = lane >> 2, tig = lane & 3;
    int row0 = blockIdx.x * 64;
    uint32_t ring_s = ring_addr(ring, wid, lane);

    bn1_s[tid] = bn1[tid];
    bn2_s[tid] = bn2[tid];

    int e = tid >> 2, jq = tid & 3;
    int node = row0 + e; if (node >= NN) node = NN - 1;

    // ---- stage 1: hidden = silu([h, agg] @ Wn1^T + bn1), K=512 in 2 passes ----
    build_a_frags(a_s, &h[node * 256], e, jq);
    __syncthreads();

    float d[4][4][4];
    zero_d(d);
    mma_gemm_cp<32>(a_s, ring_s, g_Wn1F, wid * 4, 0, d, lane);
    __syncthreads();                                  // done reading h frags

    build_a_frags(a_s, &g_agg[node * 256], e, jq);
    __syncthreads();                                  // publish agg frags
    mma_gemm_cp<32>(a_s, ring_s, g_Wn1F, wid * 4, 8, d, lane);
    __syncthreads();                                  // done reading agg frags

    // epilogue: silu -> a_s fragments (rna)
#pragma unroll
    for (int mt = 0; mt < 4; mt++) {
        int e_lo = mt * 16 + gid;
#pragma unroll
        for (int nt = 0; nt < 4; nt++) {
            int colb = wid * 32 + nt * 8 + 2 * tig;
#pragma unroll
            for (int q = 0; q < 4; q++) {
                int er = e_lo + (q >> 1) * 8;
                int col = colb + (q & 1);
                float v = silu_f(d[mt][nt][q] + bn1_s[col]);
                a_s[afrag_idx(er, col)] = __uint_as_float(tf32_rna(v));
            }
        }
    }
    __syncthreads();                                  // publish hidden frags

    // ---- stage 2: h_out = hidden @ Wn2^T + bn2 + h ----
    zero_d(d);
    mma_gemm_cp<32>(a_s, ring_s, g_Wn2F, wid * 4, 0, d, lane);
#pragma unroll
    for (int mt = 0; mt < 4; mt++) {
        int row = row0 + mt * 16 + gid;
#pragma unroll
        for (int nt = 0; nt < 4; nt++) {
            int col = wid * 32 + nt * 8 + 2 * tig;
            if (row < NN) {
                float2 hv = *(const float2*)&h[row * 256 + col];
                *(float2*)&out[row * 256 + col] =
                    make_float2(d[mt][nt][0] + bn2_s[col] + hv.x,
                                d[mt][nt][1] + bn2_s[col + 1] + hv.y);
            }
            if (row + 8 < NN) {
                float2 hv = *(const float2*)&h[(row + 8) * 256 + col];
                *(float2*)&out[(row + 8) * 256 + col] =
                    make_float2(d[mt][nt][2] + bn2_s[col] + hv.x,
                                d[mt][nt][3] + bn2_s[col + 1] + hv.y);
            }
        }
    }
}

// ---------------- coord finalize ----------------
__global__ void coord_kernel(const float* __restrict__ coord, float* __restrict__ out) {
    int i = blockIdx.x * blockDim.x + threadIdx.x;
    if (i < NN) {
        float cnt = g_cnt[i];
        if (cnt < 1.0f) cnt = 1.0f;
        float inv = 1.0f / cnt;
        out[NN * 256 + i * 3]     = coord[i * 3]     + g_csum[i * 3]     * inv;
        out[NN * 256 + i * 3 + 1] = coord[i * 3 + 1] + g_csum[i * 3 + 1] * inv;
        out[NN * 256 + i * 3 + 2] = coord[i * 3 + 2] + g_csum[i * 3 + 2] * inv;
    }
}

// ---------------- launch ----------------
extern "C" void kernel_launch(void* const* d_in, const int* in_sizes, int n_in,
                              void* d_out, int out_size) {
    const float* h    = (const float*)d_in[0];
    const int*   eidx = (const int*)d_in[1];
    const float* coord = (const float*)d_in[2];
    const float* We1  = (const float*)d_in[3];
    const float* be1  = (const float*)d_in[4];
    const float* We2  = (const float*)d_in[5];
    const float* be2  = (const float*)d_in[6];
    const float* Wn1  = (const float*)d_in[7];
    const float* bn1  = (const float*)d_in[8];
    const float* Wn2  = (const float*)d_in[9];
    const float* bn2  = (const float*)d_in[10];
    const float* Wc1  = (const float*)d_in[11];
    const float* bc1  = (const float*)d_in[12];
    const float* Wc2  = (const float*)d_in[13];
    float* out = (float*)d_out;

    cudaFuncSetAttribute(gemm_ab, cudaFuncAttributeMaxDynamicSharedMemorySize,
                         AB_SMEM_BYTES);
    cudaFuncSetAttribute(edge_kernel, cudaFuncAttributeMaxDynamicSharedMemorySize,
                         EDGE_SMEM_BYTES);
    cudaFuncSetAttribute(node_kernel, cudaFuncAttributeMaxDynamicSharedMemorySize,
                         NODE_SMEM_BYTES);

    prep_kernel<<<512, 256>>>(We1, We2, Wc1, Wn1, Wn2);
    gemm_ab<<<dim3(782, 2), 256, AB_SMEM_BYTES>>>(h);
    edge_kernel<<<NE / 64, 256, EDGE_SMEM_BYTES>>>(eidx, coord, be1, be2, bc1, Wc2);
    node_kernel<<<782, 256, NODE_SMEM_BYTES>>>(h, bn1, bn2, out);
    coord_kernel<<<(NN + 255) / 256, 256>>>(coord, out);
}

// round 13
// speedup vs baseline: 1.1479x; 1.1479x over previous
#include <cuda_runtime.h>
#include <cstdint>

#define NN 50000
#define NE 800000

// ---------------- device scratch ----------------
__device__ float g_AB[NN * 512];      // [n][0:256)=h@We1a^T, [256:512)=h@We1b^T
__device__ float g_agg[NN * 256];
__device__ float g_csum[NN * 3];
__device__ float g_cnt[NN];
__device__ float g_wr[256];
// fragment-ordered tf32 weights, B-fragment of mma.m16n8k8:
//   index = ((kb*4 + k8)*NS + n8)*64 + lane*2 + i
//   holds B[k][n], k = kb*32 + k8*8 + (lane&3) + 4*i, n = n8*8 + (lane>>2)
__device__ float g_W2F[256 * 256];    // NS=32
__device__ float g_Wc1F[256 * 256];   // NS=32
__device__ float g_W1F[256 * 512];    // NS=64 (n = 0..511 over [We1a|We1b])
__device__ float g_Wn1F[512 * 256];   // NS=32, kb=0..15 (K=512)
__device__ float g_Wn2F[256 * 256];   // NS=32

__device__ __forceinline__ float silu_f(float v) {
    return __fdividef(v, 1.0f + __expf(-v));
}
__device__ __forceinline__ uint32_t tf32_rna(float v) {
    uint32_t r;
    asm("cvt.rna.tf32.f32 %0, %1;" : "=r"(r) : "f"(v));
    return r;
}
__device__ __forceinline__ void mma_tf32(float d[4], uint32_t a0, uint32_t a1,
                                         uint32_t a2, uint32_t a3,
                                         uint32_t b0, uint32_t b1) {
    asm volatile(
        "mma.sync.aligned.m16n8k8.row.col.f32.tf32.tf32.f32 "
        "{%0,%1,%2,%3},{%4,%5,%6,%7},{%8,%9},{%0,%1,%2,%3};"
        : "+f"(d[0]), "+f"(d[1]), "+f"(d[2]), "+f"(d[3])
        : "r"(a0), "r"(a1), "r"(a2), "r"(a3), "r"(b0), "r"(b1));
}
__device__ __forceinline__ void red_add_v4(float* p, float a, float b, float c, float e) {
    asm volatile("red.global.add.v4.f32 [%0], {%1,%2,%3,%4};"
                 :: "l"(p), "f"(a), "f"(b), "f"(c), "f"(e) : "memory");
}

// ---------------- prep: fragment-order weights, zero accumulators ----------------
__global__ void prep_kernel(const float* __restrict__ We1,
                            const float* __restrict__ We2,
                            const float* __restrict__ Wc1,
                            const float* __restrict__ Wn1,
                            const float* __restrict__ Wn2) {
    int i = blockIdx.x * blockDim.x + threadIdx.x;
    int stride = gridDim.x * blockDim.x;
    for (int t = i; t < NN * 256; t += stride) g_agg[t] = 0.0f;
    for (int t = i; t < NN * 3; t += stride) g_csum[t] = 0.0f;
    for (int t = i; t < NN; t += stride) g_cnt[t] = 0.0f;
    for (int t = i; t < 256; t += stride) g_wr[t] = We1[t * 513 + 512];
    // NS=32 fragment tables (256x256)
    for (int t = i; t < 65536; t += stride) {
        int ii = t & 1;
        int lanei = (t >> 1) & 31;
        int n8 = (t >> 6) & 31;
        int k8 = (t >> 11) & 3;
        int kb = t >> 13;
        int k = kb * 32 + k8 * 8 + (lanei & 3) + 4 * ii;
        int o = n8 * 8 + (lanei >> 2);
        g_W2F[t]  = __uint_as_float(tf32_rna(We2[o * 256 + k]));
        g_Wc1F[t] = __uint_as_float(tf32_rna(Wc1[o * 256 + k]));
        g_Wn2F[t] = __uint_as_float(tf32_rna(Wn2[o * 256 + k]));
    }
    // g_W1F: NS=64, K=256, n=0..511 over [We1a | We1b]
    for (int t = i; t < 131072; t += stride) {
        int ii = t & 1;
        int lanei = (t >> 1) & 31;
        int n8 = (t >> 6) & 63;
        int k8 = (t >> 12) & 3;
        int kb = t >> 14;
        int k = kb * 32 + k8 * 8 + (lanei & 3) + 4 * ii;
        int j = n8 * 8 + (lanei >> 2);
        float v = (j < 256) ? We1[j * 513 + k] : We1[(j - 256) * 513 + 256 + k];
        g_W1F[t] = __uint_as_float(tf32_rna(v));
    }
    // g_Wn1F: NS=32, K=512 (kb = 0..15)
    for (int t = i; t < 131072; t += stride) {
        int ii = t & 1;
        int lanei = (t >> 1) & 31;
        int n8 = (t >> 6) & 31;
        int k8 = (t >> 11) & 3;
        int kb = t >> 13;
        int k = kb * 32 + k8 * 8 + (lanei & 3) + 4 * ii;
        int o = n8 * 8 + (lanei >> 2);
        g_Wn1F[t] = __uint_as_float(tf32_rna(Wn1[o * 512 + k]));
    }
}

// ---------------- shared mma building blocks ----------------
// 64 x 32 x 256-chunk per-warp tf32 GEMM accumulate. Warp covers ALL 64 rows
// (4 A frags from SMEM, broadcast across warps) x 32 cols (4 B frags via
// coalesced LDG.64). B prefetch at DISTANCE 2 with two live buffers:
// ks loop unrolled by 2; even steps consume Be (refilled for ks+2),
// odd steps consume Bo (refilled for ks+3). Same register count as the
// distance-1 version (no Bc=Bn copies). No barriers inside.
// a_s: A fragments [ks(32)][mt(4)][lane(32)][4].
template <int NS>
__device__ __forceinline__ void mma_gemm_w(
    const float* a_s, const float* __restrict__ WF, int n8base, int kb0,
    float d[4][4][4], int lane) {
    const float* bb = WF + ((size_t)(kb0 * 4 * NS + n8base)) * 64 + lane * 2;
    const size_t kstride = (size_t)NS * 64;
    uint2 Be[4], Bo[4];
#pragma unroll
    for (int nt = 0; nt < 4; nt++) {
        Be[nt] = *(const uint2*)(bb + (size_t)nt * 64);
        Bo[nt] = *(const uint2*)(bb + kstride + (size_t)nt * 64);
    }
#pragma unroll
    for (int ks = 0; ks < 32; ks += 2) {
        // even step: consume Be
        {
            uint4 A[4];
#pragma unroll
            for (int mt = 0; mt < 4; mt++)
                A[mt] = *(const uint4*)&a_s[((ks * 4 + mt) * 32 + lane) * 4];
#pragma unroll
            for (int nt = 0; nt < 4; nt++)
#pragma unroll
                for (int mt = 0; mt < 4; mt++)
                    mma_tf32(d[mt][nt], A[mt].x, A[mt].y, A[mt].z, A[mt].w,
                             Be[nt].x, Be[nt].y);
        }
        if (ks + 2 < 32) {    // refill Be for ks+2 (distance 2)
            const float* src = bb + (size_t)(ks + 2) * kstride;
#pragma unroll
            for (int nt = 0; nt < 4; nt++)
                Be[nt] = *(const uint2*)(src + (size_t)nt * 64);
        }
        // odd step: consume Bo
        {
            uint4 A[4];
#pragma unroll
            for (int mt = 0; mt < 4; mt++)
                A[mt] = *(const uint4*)&a_s[(((ks + 1) * 4 + mt) * 32 + lane) * 4];
#pragma unroll
            for (int nt = 0; nt < 4; nt++)
#pragma unroll
                for (int mt = 0; mt < 4; mt++)
                    mma_tf32(d[mt][nt], A[mt].x, A[mt].y, A[mt].z, A[mt].w,
                             Bo[nt].x, Bo[nt].y);
        }
        if (ks + 3 < 32) {    // refill Bo for ks+3 (distance 2)
            const float* src = bb + (size_t)(ks + 3) * kstride;
#pragma unroll
            for (int nt = 0; nt < 4; nt++)
                Bo[nt] = *(const uint2*)(src + (size_t)nt * 64);
        }
    }
}

__device__ __forceinline__ void zero_d(float d[4][4][4]) {
#pragma unroll
    for (int mt = 0; mt < 4; mt++)
#pragma unroll
        for (int nt = 0; nt < 4; nt++)
#pragma unroll
            for (int q = 0; q < 4; q++) d[mt][nt][q] = 0.0f;
}

// Build A fragments (rounded to tf32) for a 256-col row-major source.
// e = local row (0..63), jq in 0..3.
__device__ __forceinline__ void build_a_frags(float* a_s, const float* src,
                                              int e, int jq) {
    int mt = e >> 4, hi = (e >> 3) & 1, lb = (e & 7) * 4;
#pragma unroll
    for (int jb = 0; jb < 16; jb++) {
        int j = jb * 16 + jq * 4;
        float4 x = *(const float4*)&src[j];
        int ks = j >> 3, chi = (j >> 2) & 1;
        int base = ((ks * 4 + mt) * 32 + lb) * 4 + hi + 2 * chi;
        a_s[base + 0]  = __uint_as_float(tf32_rna(x.x));
        a_s[base + 4]  = __uint_as_float(tf32_rna(x.y));
        a_s[base + 8]  = __uint_as_float(tf32_rna(x.z));
        a_s[base + 12] = __uint_as_float(tf32_rna(x.w));
    }
}

// a_s fragment index for (row e, col) in MT=4 layout
__device__ __forceinline__ int afrag_idx(int e, int col) {
    int cc = col & 7, tg = cc & 3, chi2 = cc >> 2;
    return (((col >> 3) * 4 + (e >> 4)) * 32 + (e & 7) * 4 + tg) * 4
         + ((e >> 3) & 1) + 2 * chi2;
}

// ---------------- K1: AB = h @ [We1a^T | We1b^T]  (tf32 mma) ----------------
#define AB_SMEM_FLOATS (16384)
#define AB_SMEM_BYTES  (AB_SMEM_FLOATS * 4)

__global__ __launch_bounds__(256, 2) void gemm_ab(const float* __restrict__ h) {
    extern __shared__ float sm[];
    float* a_s = sm;           // 16384

    int tid = threadIdx.x;
    int lane = tid & 31, wid = tid >> 5;
    int gid = lane >> 2, tig = lane & 3;
    int row0 = blockIdx.x * 64;
    int jbase = blockIdx.y * 256;

    {
        int e = tid >> 2, jq = tid & 3;
        int row = row0 + e; if (row >= NN) row = NN - 1;
        build_a_frags(a_s, &h[row * 256], e, jq);
    }
    __syncthreads();

    float d[4][4][4];
    zero_d(d);
    mma_gemm_w<64>(a_s, g_W1F, blockIdx.y * 32 + wid * 4, 0, d, lane);

#pragma unroll
    for (int mt = 0; mt < 4; mt++) {
        int row = row0 + mt * 16 + gid;
#pragma unroll
        for (int nt = 0; nt < 4; nt++) {
            int col = jbase + wid * 32 + nt * 8 + 2 * tig;
            if (row < NN)
                *(float2*)&g_AB[row * 512 + col] =
                    make_float2(d[mt][nt][0], d[mt][nt][1]);
            if (row + 8 < NN)
                *(float2*)&g_AB[(row + 8) * 512 + col] =
                    make_float2(d[mt][nt][2], d[mt][nt][3]);
        }
    }
}

// ---------------- edge kernel: 64 edges/CTA, 256 threads ----------------
#define EDGE_SMEM_FLOATS (16384 + 5*256 + 64 + 192 + 64 + 128)
#define EDGE_SMEM_BYTES  (EDGE_SMEM_FLOATS * 4)

__global__ __launch_bounds__(256, 2) void edge_kernel(
    const int* __restrict__ eidx, const float* __restrict__ coord,
    const float* __restrict__ be1, const float* __restrict__ be2,
    const float* __restrict__ bc1, const float* __restrict__ Wc2) {
    extern __shared__ float sm[];
    float* a_s   = sm;                       // 16384
    float* wr_s  = a_s + 16384;
    float* be1_s = wr_s + 256;
    float* be2_s = be1_s + 256;
    float* bc1_s = be2_s + 256;
    float* wc2_s = bc1_s + 256;
    float* rad_s = wc2_s + 256;              // 64
    float* diff_s = rad_s + 64;              // 192
    float* psum_s = diff_s + 192;            // 64
    int*   rows_s = (int*)(psum_s + 64);     // 64
    int*   cols_s = rows_s + 64;             // 64

    int tid = threadIdx.x;
    int lane = tid & 31, wid = tid >> 5;
    int gid = lane >> 2, tig = lane & 3;
    int e0 = blockIdx.x * 64;

    wr_s[tid]  = g_wr[tid];
    be1_s[tid] = be1[tid];
    be2_s[tid] = be2[tid];
    bc1_s[tid] = bc1[tid];
    wc2_s[tid] = Wc2[tid];
    if (tid < 64) {
        psum_s[tid] = 0.0f;
        int r = eidx[e0 + tid], c = eidx[NE + e0 + tid];
        rows_s[tid] = r; cols_s[tid] = c;
        float dx = coord[r * 3]     - coord[c * 3];
        float dy = coord[r * 3 + 1] - coord[c * 3 + 1];
        float dz = coord[r * 3 + 2] - coord[c * 3 + 2];
        diff_s[tid * 3]     = dx;
        diff_s[tid * 3 + 1] = dy;
        diff_s[tid * 3 + 2] = dz;
        rad_s[tid] = dx * dx + dy * dy + dz * dz;
    }
    __syncthreads();

    // ---- stage 1: m = silu(A[row]+B[col]+rad*wr+be1), A-fragment layout (rna) ----
    {
        int e = tid >> 2, jq = tid & 3;
        int rrow = rows_s[e], ccol = cols_s[e];
        float rad = rad_s[e];
        const float* ap = &g_AB[rrow * 512];
        const float* bp = &g_AB[ccol * 512 + 256];
        int mt = e >> 4, hi = (e >> 3) & 1, lb = (e & 7) * 4;
#pragma unroll
        for (int jb = 0; jb < 16; jb++) {
            int j = jb * 16 + jq * 4;
            float4 a  = *(const float4*)&ap[j];
            float4 b  = *(const float4*)&bp[j];
            float4 w  = *(const float4*)&wr_s[j];
            float4 bb = *(const float4*)&be1_s[j];
            float mv[4];
            mv[0] = silu_f(a.x + b.x + rad * w.x + bb.x);
            mv[1] = silu_f(a.y + b.y + rad * w.y + bb.y);
            mv[2] = silu_f(a.z + b.z + rad * w.z + bb.z);
            mv[3] = silu_f(a.w + b.w + rad * w.w + bb.w);
            int ks = j >> 3, chi = (j >> 2) & 1;
            int base = ((ks * 4 + mt) * 32 + lb) * 4 + hi + 2 * chi;
#pragma unroll
            for (int q = 0; q < 4; q++)
                a_s[base + q * 4] = __uint_as_float(tf32_rna(mv[q]));
        }
    }
    __syncthreads();

    float d[4][4][4];

    // ---- stage 2: ef = silu(m @ We2^T + be2) ----
    zero_d(d);
    mma_gemm_w<32>(a_s, g_W2F, wid * 4, 0, d, lane);
    __syncthreads();   // all warps done reading m before a_s is overwritten
#pragma unroll
    for (int mt = 0; mt < 4; mt++) {
        int e_lo = mt * 16 + gid;
#pragma unroll
        for (int nt = 0; nt < 4; nt++) {
            int colb = wid * 32 + nt * 8 + 2 * tig;
#pragma unroll
            for (int q = 0; q < 4; q++) {
                int e = e_lo + (q >> 1) * 8;
                int col = colb + (q & 1);
                float v = silu_f(d[mt][nt][q] + be2_s[col]);
                a_s[afrag_idx(e, col)] = v;  // raw f32; mma truncates later
            }
        }
    }
    __syncthreads();   // publish ef

    // ---- agg scatter: 4 cols per vector RED ----
    {
        int e = tid >> 2, cg = tid & 3;
        int r = rows_s[e];
        int mt = e >> 4, hi8 = (e >> 3) & 1, lb = (e & 7) * 4;
#pragma unroll
        for (int b = 0; b < 16; b++) {
            int col = cg * 64 + b * 4;
            int ks = col >> 3, chi2 = (col >> 2) & 1;
            int base = ((ks * 4 + mt) * 32 + lb) * 4 + hi8 + 2 * chi2;
            red_add_v4(&g_agg[r * 256 + col],
                       a_s[base], a_s[base + 4], a_s[base + 8], a_s[base + 12]);
        }
    }

    // ---- stage 3: phi = silu(ef @ Wc1^T + bc1) . Wc2 ; coord scatter ----
    zero_d(d);
    mma_gemm_w<32>(a_s, g_Wc1F, wid * 4, 0, d, lane);
    float s[4][2];
#pragma unroll
    for (int mt = 0; mt < 4; mt++) { s[mt][0] = 0.0f; s[mt][1] = 0.0f; }
#pragma unroll
    for (int mt = 0; mt < 4; mt++)
#pragma unroll
        for (int nt = 0; nt < 4; nt++) {
            int colb = wid * 32 + nt * 8 + 2 * tig;
            float w0 = wc2_s[colb], w1 = wc2_s[colb + 1];
            float b0 = bc1_s[colb], b1 = bc1_s[colb + 1];
            s[mt][0] += silu_f(d[mt][nt][0] + b0) * w0 + silu_f(d[mt][nt][1] + b1) * w1;
            s[mt][1] += silu_f(d[mt][nt][2] + b0) * w0 + silu_f(d[mt][nt][3] + b1) * w1;
        }
#pragma unroll
    for (int off = 1; off <= 2; off <<= 1)
#pragma unroll
        for (int mt = 0; mt < 4; mt++) {
            s[mt][0] += __shfl_xor_sync(0xffffffffu, s[mt][0], off);
            s[mt][1] += __shfl_xor_sync(0xffffffffu, s[mt][1], off);
        }
    if (tig == 0) {
#pragma unroll
        for (int mt = 0; mt < 4; mt++) {
            atomicAdd(&psum_s[mt * 16 + gid],     s[mt][0]);
            atomicAdd(&psum_s[mt * 16 + 8 + gid], s[mt][1]);
        }
    }
    __syncthreads();
    if (tid < 64) {
        float phi = psum_s[tid];
        int r = rows_s[tid];
        atomicAdd(&g_csum[r * 3],     diff_s[tid * 3]     * phi);
        atomicAdd(&g_csum[r * 3 + 1], diff_s[tid * 3 + 1] * phi);
        atomicAdd(&g_csum[r * 3 + 2], diff_s[tid * 3 + 2] * phi);
        atomicAdd(&g_cnt[r], 1.0f);
    }
}

// ---------------- node MLP + residual (tf32 mma) ----------------
#define NODE_SMEM_FLOATS (16384 + 512)
#define NODE_SMEM_BYTES  (NODE_SMEM_FLOATS * 4)

__global__ __launch_bounds__(256, 2) void node_kernel(
    const float* __restrict__ h, const float* __restrict__ bn1,
    const float* __restrict__ bn2, float* __restrict__ out) {
    extern __shared__ float sm[];
    float* a_s   = sm;            // 16384
    float* bn1_s = a_s + 16384;   // 256
    float* bn2_s = bn1_s + 256;   // 256

    int tid = threadIdx.x;
    int lane = tid & 31, wid = tid >> 5;
    int gid = lane >> 2, tig = lane & 3;
    int row0 = blockIdx.x * 64;

    bn1_s[tid] = bn1[tid];
    bn2_s[tid] = bn2[tid];

    int e = tid >> 2, jq = tid & 3;
    int node = row0 + e; if (node >= NN) node = NN - 1;

    // ---- stage 1: hidden = silu([h, agg] @ Wn1^T + bn1), K=512 in 2 passes ----
    build_a_frags(a_s, &h[node * 256], e, jq);
    __syncthreads();

    float d[4][4][4];
    zero_d(d);
    mma_gemm_w<32>(a_s, g_Wn1F, wid * 4, 0, d, lane);
    __syncthreads();                                  // done reading h frags

    build_a_frags(a_s, &g_agg[node * 256], e, jq);
    __syncthreads();                                  // publish agg frags
    mma_gemm_w<32>(a_s, g_Wn1F, wid * 4, 8, d, lane);
    __syncthreads();                                  // done reading agg frags

    // epilogue: silu -> a_s fragments (rna)
#pragma unroll
    for (int mt = 0; mt < 4; mt++) {
        int e_lo = mt * 16 + gid;
#pragma unroll
        for (int nt = 0; nt < 4; nt++) {
            int colb = wid * 32 + nt * 8 + 2 * tig;
#pragma unroll
            for (int q = 0; q < 4; q++) {
                int er = e_lo + (q >> 1) * 8;
                int col = colb + (q & 1);
                float v = silu_f(d[mt][nt][q] + bn1_s[col]);
                a_s[afrag_idx(er, col)] = __uint_as_float(tf32_rna(v));
            }
        }
    }
    __syncthreads();                                  // publish hidden frags

    // ---- stage 2: h_out = hidden @ Wn2^T + bn2 + h ----
    zero_d(d);
    mma_gemm_w<32>(a_s, g_Wn2F, wid * 4, 0, d, lane);
#pragma unroll
    for (int mt = 0; mt < 4; mt++) {
        int row = row0 + mt * 16 + gid;
#pragma unroll
        for (int nt = 0; nt < 4; nt++) {
            int col = wid * 32 + nt * 8 + 2 * tig;
            if (row < NN) {
                float2 hv = *(const float2*)&h[row * 256 + col];
                *(float2*)&out[row * 256 + col] =
                    make_float2(d[mt][nt][0] + bn2_s[col] + hv.x,
                                d[mt][nt][1] + bn2_s[col + 1] + hv.y);
            }
            if (row + 8 < NN) {
                float2 hv = *(const float2*)&h[(row + 8) * 256 + col];
                *(float2*)&out[(row + 8) * 256 + col] =
                    make_float2(d[mt][nt][2] + bn2_s[col] + hv.x,
                                d[mt][nt][3] + bn2_s[col + 1] + hv.y);
            }
        }
    }
}

// ---------------- coord finalize ----------------
__global__ void coord_kernel(const float* __restrict__ coord, float* __restrict__ out) {
    int i = blockIdx.x * blockDim.x + threadIdx.x;
    if (i < NN) {
        float cnt = g_cnt[i];
        if (cnt < 1.0f) cnt = 1.0f;
        float inv = 1.0f / cnt;
        out[NN * 256 + i * 3]     = coord[i * 3]     + g_csum[i * 3]     * inv;
        out[NN * 256 + i * 3 + 1] = coord[i * 3 + 1] + g_csum[i * 3 + 1] * inv;
        out[NN * 256 + i * 3 + 2] = coord[i * 3 + 2] + g_csum[i * 3 + 2] * inv;
    }
}

// ---------------- launch ----------------
extern "C" void kernel_launch(void* const* d_in, const int* in_sizes, int n_in,
                              void* d_out, int out_size) {
    const float* h    = (const float*)d_in[0];
    const int*   eidx = (const int*)d_in[1];
    const float* coord = (const float*)d_in[2];
    const float* We1  = (const float*)d_in[3];
    const float* be1  = (const float*)d_in[4];
    const float* We2  = (const float*)d_in[5];
    const float* be2  = (const float*)d_in[6];
    const float* Wn1  = (const float*)d_in[7];
    const float* bn1  = (const float*)d_in[8];
    const float* Wn2  = (const float*)d_in[9];
    const float* bn2  = (const float*)d_in[10];
    const float* Wc1  = (const float*)d_in[11];
    const float* bc1  = (const float*)d_in[12];
    const float* Wc2  = (const float*)d_in[13];
    float* out = (float*)d_out;

    cudaFuncSetAttribute(gemm_ab, cudaFuncAttributeMaxDynamicSharedMemorySize,
                         AB_SMEM_BYTES);
    cudaFuncSetAttribute(edge_kernel, cudaFuncAttributeMaxDynamicSharedMemorySize,
                         EDGE_SMEM_BYTES);
    cudaFuncSetAttribute(node_kernel, cudaFuncAttributeMaxDynamicSharedMemorySize,
                         NODE_SMEM_BYTES);

    prep_kernel<<<512, 256>>>(We1, We2, Wc1, Wn1, Wn2);
    gemm_ab<<<dim3(782, 2), 256, AB_SMEM_BYTES>>>(h);
    edge_kernel<<<NE / 64, 256, EDGE_SMEM_BYTES>>>(eidx, coord, be1, be2, bc1, Wc2);
    node_kernel<<<782, 256, NODE_SMEM_BYTES>>>(h, bn1, bn2, out);
    coord_kernel<<<(NN + 255) / 256, 256>>>(coord, out);
}

// round 16
// speedup vs baseline: 1.2094x; 1.0536x over previous
#include <cuda_runtime.h>
#include <cstdint>

#define NN 50000
#define NE 800000

// ---------------- device scratch ----------------
__device__ float g_AB[NN * 512];      // [n][0:256)=h@We1a^T, [256:512)=h@We1b^T
__device__ float g_agg[NN * 256];
__device__ float g_csum[NN * 3];
__device__ float g_cnt[NN];
__device__ float g_wr[256];
// fragment-ordered tf32 weights, B-fragment of mma.m16n8k8:
//   index = ((kb*4 + k8)*NS + n8)*64 + lane*2 + i
//   holds B[k][n], k = kb*32 + k8*8 + (lane&3) + 4*i, n = n8*8 + (lane>>2)
__device__ float g_W2F[256 * 256];    // NS=32
__device__ float g_W1F[256 * 512];    // NS=64 (n = 0..511 over [We1a|We1b])
__device__ float g_Wn1F[512 * 256];   // NS=32, kb=0..15 (K=512)
__device__ float g_Wn2F[256 * 256];   // NS=32
// bf16-packed Wc1 B-fragments for mma.m16n8k16 (edge GEMM3):
//   index = ((s*32 + n8)*32 + lane)*2 + r ; holds pack(Wc1[n][k], Wc1[n][k+1])
//   n = n8*8 + lane>>2 ; k = s*16 + (lane&3)*2 + r*8
__device__ uint32_t g_Wc1B[32768];

__device__ __forceinline__ float silu_f(float v) {
    return __fdividef(v, 1.0f + __expf(-v));
}
__device__ __forceinline__ uint32_t tf32_rna(float v) {
    uint32_t r;
    asm("cvt.rna.tf32.f32 %0, %1;" : "=r"(r) : "f"(v));
    return r;
}
__device__ __forceinline__ float tf32f(float v) {
    return __uint_as_float(tf32_rna(v));
}
__device__ __forceinline__ uint32_t bf16pack(float lo, float hi) {
    uint32_t r;   // first src operand -> upper half
    asm("cvt.rn.bf16x2.f32 %0, %1, %2;" : "=r"(r) : "f"(hi), "f"(lo));
    return r;
}
__device__ __forceinline__ void mma_tf32(float d[4], uint32_t a0, uint32_t a1,
                                         uint32_t a2, uint32_t a3,
                                         uint32_t b0, uint32_t b1) {
    asm volatile(
        "mma.sync.aligned.m16n8k8.row.col.f32.tf32.tf32.f32 "
        "{%0,%1,%2,%3},{%4,%5,%6,%7},{%8,%9},{%0,%1,%2,%3};"
        : "+f"(d[0]), "+f"(d[1]), "+f"(d[2]), "+f"(d[3])
        : "r"(a0), "r"(a1), "r"(a2), "r"(a3), "r"(b0), "r"(b1));
}
__device__ __forceinline__ void mma_bf16(float d[4], uint32_t a0, uint32_t a1,
                                         uint32_t a2, uint32_t a3,
                                         uint32_t b0, uint32_t b1) {
    asm volatile(
        "mma.sync.aligned.m16n8k16.row.col.f32.bf16.bf16.f32 "
        "{%0,%1,%2,%3},{%4,%5,%6,%7},{%8,%9},{%0,%1,%2,%3};"
        : "+f"(d[0]), "+f"(d[1]), "+f"(d[2]), "+f"(d[3])
        : "r"(a0), "r"(a1), "r"(a2), "r"(a3), "r"(b0), "r"(b1));
}
__device__ __forceinline__ void red_add_v4(float* p, float a, float b, float c, float e) {
    asm volatile("red.global.add.v4.f32 [%0], {%1,%2,%3,%4};"
                 :: "l"(p), "f"(a), "f"(b), "f"(c), "f"(e) : "memory");
}

// ---------------- prep: fragment-order weights, zero accumulators ----------------
__global__ void prep_kernel(const float* __restrict__ We1,
                            const float* __restrict__ We2,
                            const float* __restrict__ Wc1,
                            const float* __restrict__ Wn1,
                            const float* __restrict__ Wn2) {
    int i = blockIdx.x * blockDim.x + threadIdx.x;
    int stride = gridDim.x * blockDim.x;
    for (int t = i; t < NN * 256; t += stride) g_agg[t] = 0.0f;
    for (int t = i; t < NN * 3; t += stride) g_csum[t] = 0.0f;
    for (int t = i; t < NN; t += stride) g_cnt[t] = 0.0f;
    for (int t = i; t < 256; t += stride) g_wr[t] = We1[t * 513 + 512];
    // NS=32 fragment tables (256x256)
    for (int t = i; t < 65536; t += stride) {
        int ii = t & 1;
        int lanei = (t >> 1) & 31;
        int n8 = (t >> 6) & 31;
        int k8 = (t >> 11) & 3;
        int kb = t >> 13;
        int k = kb * 32 + k8 * 8 + (lanei & 3) + 4 * ii;
        int o = n8 * 8 + (lanei >> 2);
        g_W2F[t]  = tf32f(We2[o * 256 + k]);
        g_Wn2F[t] = tf32f(Wn2[o * 256 + k]);
    }
    // bf16 Wc1 B-fragments (m16n8k16)
    for (int t = i; t < 32768; t += stride) {
        int r = t & 1;
        int lanei = (t >> 1) & 31;
        int n8 = (t >> 6) & 31;
        int s = t >> 11;
        int n = n8 * 8 + (lanei >> 2);
        int k = s * 16 + (lanei & 3) * 2 + r * 8;
        g_Wc1B[((s * 32 + n8) * 32 + lanei) * 2 + r] =
            bf16pack(Wc1[n * 256 + k], Wc1[n * 256 + k + 1]);
    }
    // g_W1F: NS=64, K=256, n=0..511 over [We1a | We1b]
    for (int t = i; t < 131072; t += stride) {
        int ii = t & 1;
        int lanei = (t >> 1) & 31;
        int n8 = (t >> 6) & 63;
        int k8 = (t >> 12) & 3;
        int kb = t >> 14;
        int k = kb * 32 + k8 * 8 + (lanei & 3) + 4 * ii;
        int j = n8 * 8 + (lanei >> 2);
        float v = (j < 256) ? We1[j * 513 + k] : We1[(j - 256) * 513 + 256 + k];
        g_W1F[t] = tf32f(v);
    }
    // g_Wn1F: NS=32, K=512 (kb = 0..15)
    for (int t = i; t < 131072; t += stride) {
        int ii = t & 1;
        int lanei = (t >> 1) & 31;
        int n8 = (t >> 6) & 31;
        int k8 = (t >> 11) & 3;
        int kb = t >> 13;
        int k = kb * 32 + k8 * 8 + (lanei & 3) + 4 * ii;
        int o = n8 * 8 + (lanei >> 2);
        g_Wn1F[t] = tf32f(Wn1[o * 512 + k]);
    }
}

// ---------------- shared mma building blocks ----------------
// 64 x 32 x 256-chunk per-warp tf32 GEMM accumulate (R10-verified).
template <int NS>
__device__ __forceinline__ void mma_gemm_w(
    const float* a_s, const float* __restrict__ WF, int n8base, int kb0,
    float d[4][4][4], int lane) {
    const float* bb = WF + ((size_t)(kb0 * 4 * NS + n8base)) * 64 + lane * 2;
    const size_t kstride = (size_t)NS * 64;
    uint2 Bc[4], Bn[4];
#pragma unroll
    for (int nt = 0; nt < 4; nt++)
        Bc[nt] = *(const uint2*)(bb + (size_t)nt * 64);
#pragma unroll
    for (int ks = 0; ks < 32; ks++) {
        if (ks < 31) {
            const float* nb = bb + (size_t)(ks + 1) * kstride;
#pragma unroll
            for (int nt = 0; nt < 4; nt++)
                Bn[nt] = *(const uint2*)(nb + (size_t)nt * 64);
        }
        uint4 A[4];
#pragma unroll
        for (int mt = 0; mt < 4; mt++)
            A[mt] = *(const uint4*)&a_s[((ks * 4 + mt) * 32 + lane) * 4];
#pragma unroll
        for (int nt = 0; nt < 4; nt++)
#pragma unroll
            for (int mt = 0; mt < 4; mt++)
                mma_tf32(d[mt][nt], A[mt].x, A[mt].y, A[mt].z, A[mt].w,
                         Bc[nt].x, Bc[nt].y);
#pragma unroll
        for (int nt = 0; nt < 4; nt++) Bc[nt] = Bn[nt];
    }
}

// 64 x 32 x 256 bf16 GEMM (m16n8k16, 16 K-steps). A packed in efb (SMEM u32),
// layout [s(16)][mt(4)][lane(32)][r(4)]; B from g_Wc1B (global, coalesced).
__device__ __forceinline__ void mma_gemm_b16(
    const uint32_t* efb, const uint32_t* __restrict__ WB, int n8base,
    float d[4][4][4], int lane) {
    const uint32_t* bb = WB + ((size_t)n8base * 32 + lane) * 2;
    uint2 Bc[4], Bn[4];
#pragma unroll
    for (int nt = 0; nt < 4; nt++)
        Bc[nt] = *(const uint2*)(bb + nt * 64);
#pragma unroll
    for (int s = 0; s < 16; s++) {
        if (s < 15) {
            const uint32_t* nb = bb + (size_t)(s + 1) * 2048;
#pragma unroll
            for (int nt = 0; nt < 4; nt++)
                Bn[nt] = *(const uint2*)(nb + nt * 64);
        }
        uint4 A[4];
#pragma unroll
        for (int mt = 0; mt < 4; mt++)
            A[mt] = *(const uint4*)&efb[((s * 4 + mt) * 32 + lane) * 4];
#pragma unroll
        for (int nt = 0; nt < 4; nt++)
#pragma unroll
            for (int mt = 0; mt < 4; mt++)
                mma_bf16(d[mt][nt], A[mt].x, A[mt].y, A[mt].z, A[mt].w,
                         Bc[nt].x, Bc[nt].y);
#pragma unroll
        for (int nt = 0; nt < 4; nt++) Bc[nt] = Bn[nt];
    }
}

__device__ __forceinline__ void zero_d(float d[4][4][4]) {
#pragma unroll
    for (int mt = 0; mt < 4; mt++)
#pragma unroll
        for (int nt = 0; nt < 4; nt++)
#pragma unroll
            for (int q = 0; q < 4; q++) d[mt][nt][q] = 0.0f;
}

__device__ __forceinline__ void build_a_frags(float* a_s, const float* src,
                                              int e, int jq) {
    int mt = e >> 4, hi = (e >> 3) & 1, lb = (e & 7) * 4;
#pragma unroll
    for (int jb = 0; jb < 16; jb++) {
        int j = jb * 16 + jq * 4;
        float4 x = *(const float4*)&src[j];
        int ks = j >> 3, chi = (j >> 2) & 1;
        int base = ((ks * 4 + mt) * 32 + lb) * 4 + hi + 2 * chi;
        a_s[base + 0]  = tf32f(x.x);
        a_s[base + 4]  = tf32f(x.y);
        a_s[base + 8]  = tf32f(x.z);
        a_s[base + 12] = tf32f(x.w);
    }
}

// a_s fragment index for (row e, col) in MT=4 tf32 layout
__device__ __forceinline__ int afrag_idx(int e, int col) {
    int cc = col & 7, tg = cc & 3, chi2 = cc >> 2;
    return (((col >> 3) * 4 + (e >> 4)) * 32 + (e & 7) * 4 + tg) * 4
         + ((e >> 3) & 1) + 2 * chi2;
}
// efb index for (row e, even colpair base c0) in bf16 m16n8k16 A layout
__device__ __forceinline__ int bfrag_idx(int e, int c0) {
    int s = c0 >> 4, kk = c0 & 15;
    int r = ((e >> 3) & 1) + 2 * (kk >> 3);
    int ln = (e & 7) * 4 + ((kk >> 1) & 3);
    return ((s * 4 + (e >> 4)) * 32 + ln) * 4 + r;
}

// ---------------- K1: AB = h @ [We1a^T | We1b^T]  (tf32 mma) ----------------
#define AB_SMEM_FLOATS (16384)
#define AB_SMEM_BYTES  (AB_SMEM_FLOATS * 4)

__global__ __launch_bounds__(256, 2) void gemm_ab(const float* __restrict__ h) {
    extern __shared__ float sm[];
    float* a_s = sm;

    int tid = threadIdx.x;
    int lane = tid & 31, wid = tid >> 5;
    int gid = lane >> 2, tig = lane & 3;
    int row0 = blockIdx.x * 64;
    int jbase = blockIdx.y * 256;

    {
        int e = tid >> 2, jq = tid & 3;
        int row = row0 + e; if (row >= NN) row = NN - 1;
        build_a_frags(a_s, &h[row * 256], e, jq);
    }
    __syncthreads();

    float d[4][4][4];
    zero_d(d);
    mma_gemm_w<64>(a_s, g_W1F, blockIdx.y * 32 + wid * 4, 0, d, lane);

#pragma unroll
    for (int mt = 0; mt < 4; mt++) {
        int row = row0 + mt * 16 + gid;
#pragma unroll
        for (int nt = 0; nt < 4; nt++) {
            int col = jbase + wid * 32 + nt * 8 + 2 * tig;
            if (row < NN)
                *(float2*)&g_AB[row * 512 + col] =
                    make_float2(d[mt][nt][0], d[mt][nt][1]);
            if (row + 8 < NN)
                *(float2*)&g_AB[(row + 8) * 512 + col] =
                    make_float2(d[mt][nt][2], d[mt][nt][3]);
        }
    }
}

// ---------------- edge kernel: 64 edges/CTA, 256 threads ----------------
// floats: a_s 16384 | efb 8192 | biases 5*256 | rad 64 | diff 192 | psum 64 | idx 128
#define EDGE_SMEM_FLOATS (16384 + 8192 + 5*256 + 64 + 192 + 64 + 128)
#define EDGE_SMEM_BYTES  (EDGE_SMEM_FLOATS * 4)

__global__ __launch_bounds__(256, 2) void edge_kernel(
    const int* __restrict__ eidx, const float* __restrict__ coord,
    const float* __restrict__ be1, const float* __restrict__ be2,
    const float* __restrict__ bc1, const float* __restrict__ Wc2) {
    extern __shared__ float sm[];
    float*    a_s  = sm;                       // 16384
    uint32_t* efb  = (uint32_t*)(a_s + 16384); // 8192
    float* wr_s  = a_s + 24576;
    float* be1_s = wr_s + 256;
    float* be2_s = be1_s + 256;
    float* bc1_s = be2_s + 256;
    float* wc2_s = bc1_s + 256;
    float* rad_s = wc2_s + 256;                // 64
    float* diff_s = rad_s + 64;                // 192
    float* psum_s = diff_s + 192;              // 64
    int*   rows_s = (int*)(psum_s + 64);       // 64
    int*   cols_s = rows_s + 64;               // 64

    int tid = threadIdx.x;
    int lane = tid & 31, wid = tid >> 5;
    int gid = lane >> 2, tig = lane & 3;
    int e0 = blockIdx.x * 64;

    wr_s[tid]  = g_wr[tid];
    be1_s[tid] = be1[tid];
    be2_s[tid] = be2[tid];
    bc1_s[tid] = bc1[tid];
    wc2_s[tid] = Wc2[tid];
    if (tid < 64) {
        psum_s[tid] = 0.0f;
        int r = eidx[e0 + tid], c = eidx[NE + e0 + tid];
        rows_s[tid] = r; cols_s[tid] = c;
        float dx = coord[r * 3]     - coord[c * 3];
        float dy = coord[r * 3 + 1] - coord[c * 3 + 1];
        float dz = coord[r * 3 + 2] - coord[c * 3 + 2];
        diff_s[tid * 3]     = dx;
        diff_s[tid * 3 + 1] = dy;
        diff_s[tid * 3 + 2] = dz;
        rad_s[tid] = dx * dx + dy * dy + dz * dz;
    }
    __syncthreads();

    // ---- stage 1: m = silu(A[row]+B[col]+rad*wr+be1), tf32 A-fragment layout ----
    {
        int e = tid >> 2, jq = tid & 3;
        int rrow = rows_s[e], ccol = cols_s[e];
        float rad = rad_s[e];
        const float* ap = &g_AB[rrow * 512];
        const float* bp = &g_AB[ccol * 512 + 256];
        int mt = e >> 4, hi = (e >> 3) & 1, lb = (e & 7) * 4;
#pragma unroll
        for (int jb = 0; jb < 16; jb++) {
            int j = jb * 16 + jq * 4;
            float4 a  = *(const float4*)&ap[j];
            float4 b  = *(const float4*)&bp[j];
            float4 w  = *(const float4*)&wr_s[j];
            float4 bb = *(const float4*)&be1_s[j];
            float mv[4];
            mv[0] = silu_f(a.x + b.x + rad * w.x + bb.x);
            mv[1] = silu_f(a.y + b.y + rad * w.y + bb.y);
            mv[2] = silu_f(a.z + b.z + rad * w.z + bb.z);
            mv[3] = silu_f(a.w + b.w + rad * w.w + bb.w);
            int ks = j >> 3, chi = (j >> 2) & 1;
            int base = ((ks * 4 + mt) * 32 + lb) * 4 + hi + 2 * chi;
#pragma unroll
            for (int q = 0; q < 4; q++)
                a_s[base + q * 4] = tf32f(mv[q]);
        }
    }
    __syncthreads();

    float d[4][4][4];

    // ---- stage 2: ef = silu(m @ We2^T + be2); f32 -> a_s ; bf16 pairs -> efb ----
    zero_d(d);
    mma_gemm_w<32>(a_s, g_W2F, wid * 4, 0, d, lane);
    __syncthreads();   // all warps done reading m before a_s is overwritten
#pragma unroll
    for (int mt = 0; mt < 4; mt++) {
        int e_lo = mt * 16 + gid;
#pragma unroll
        for (int nt = 0; nt < 4; nt++) {
            int colb = wid * 32 + nt * 8 + 2 * tig;   // even
            float v[4];
#pragma unroll
            for (int q = 0; q < 4; q++)
                v[q] = silu_f(d[mt][nt][q] + be2_s[colb + (q & 1)]);
            a_s[afrag_idx(e_lo,     colb)]     = v[0];
            a_s[afrag_idx(e_lo,     colb + 1)] = v[1];
            a_s[afrag_idx(e_lo + 8, colb)]     = v[2];
            a_s[afrag_idx(e_lo + 8, colb + 1)] = v[3];
            efb[bfrag_idx(e_lo,     colb)] = bf16pack(v[0], v[1]);
            efb[bfrag_idx(e_lo + 8, colb)] = bf16pack(v[2], v[3]);
        }
    }
    __syncthreads();   // publish ef (both regions)

    // ---- agg scatter: 4 cols per vector RED (reads f32 a_s) ----
    {
        int e = tid >> 2, cg = tid & 3;
        int r = rows_s[e];
        int mt = e >> 4, hi8 = (e >> 3) & 1, lb = (e & 7) * 4;
#pragma unroll
        for (int b = 0; b < 16; b++) {
            int col = cg * 64 + b * 4;
            int ks = col >> 3, chi2 = (col >> 2) & 1;
            int base = ((ks * 4 + mt) * 32 + lb) * 4 + hi8 + 2 * chi2;
            red_add_v4(&g_agg[r * 256 + col],
                       a_s[base], a_s[base + 4], a_s[base + 8], a_s[base + 12]);
        }
    }

    // ---- stage 3 (bf16): phi = silu(ef @ Wc1^T + bc1) . Wc2 ; coord scatter ----
    zero_d(d);
    mma_gemm_b16(efb, g_Wc1B, wid * 4, d, lane);
    float s[4][2];
#pragma unroll
    for (int mt = 0; mt < 4; mt++) { s[mt][0] = 0.0f; s[mt][1] = 0.0f; }
#pragma unroll
    for (int mt = 0; mt < 4; mt++)
#pragma unroll
        for (int nt = 0; nt < 4; nt++) {
            int colb = wid * 32 + nt * 8 + 2 * tig;
            float w0 = wc2_s[colb], w1 = wc2_s[colb + 1];
            float b0 = bc1_s[colb], b1 = bc1_s[colb + 1];
            s[mt][0] += silu_f(d[mt][nt][0] + b0) * w0 + silu_f(d[mt][nt][1] + b1) * w1;
            s[mt][1] += silu_f(d[mt][nt][2] + b0) * w0 + silu_f(d[mt][nt][3] + b1) * w1;
        }
#pragma unroll
    for (int off = 1; off <= 2; off <<= 1)
#pragma unroll
        for (int mt = 0; mt < 4; mt++) {
            s[mt][0] += __shfl_xor_sync(0xffffffffu, s[mt][0], off);
            s[mt][1] += __shfl_xor_sync(0xffffffffu, s[mt][1], off);
        }
    if (tig == 0) {
#pragma unroll
        for (int mt = 0; mt < 4; mt++) {
            atomicAdd(&psum_s[mt * 16 + gid],     s[mt][0]);
            atomicAdd(&psum_s[mt * 16 + 8 + gid], s[mt][1]);
        }
    }
    __syncthreads();
    if (tid < 64) {
        float phi = psum_s[tid];
        int r = rows_s[tid];
        atomicAdd(&g_csum[r * 3],     diff_s[tid * 3]     * phi);
        atomicAdd(&g_csum[r * 3 + 1], diff_s[tid * 3 + 1] * phi);
        atomicAdd(&g_csum[r * 3 + 2], diff_s[tid * 3 + 2] * phi);
        atomicAdd(&g_cnt[r], 1.0f);
    }
}

// ---------------- node MLP + residual (tf32 mma) ----------------
#define NODE_SMEM_FLOATS (16384 + 512)
#define NODE_SMEM_BYTES  (NODE_SMEM_FLOATS * 4)

__global__ __launch_bounds__(256, 2) void node_kernel(
    const float* __restrict__ h, const float* __restrict__ bn1,
    const float* __restrict__ bn2, float* __restrict__ out) {
    extern __shared__ float sm[];
    float* a_s   = sm;
    float* bn1_s = a_s + 16384;
    float* bn2_s = bn1_s + 256;

    int tid = threadIdx.x;
    int lane = tid & 31, wid = tid >> 5;
    int gid = lane >> 2, tig = lane & 3;
    int row0 = blockIdx.x * 64;

    bn1_s[tid] = bn1[tid];
    bn2_s[tid] = bn2[tid];

    int e = tid >> 2, jq = tid & 3;
    int node = row0 + e; if (node >= NN) node = NN - 1;

    build_a_frags(a_s, &h[node * 256], e, jq);
    __syncthreads();

    float d[4][4][4];
    zero_d(d);
    mma_gemm_w<32>(a_s, g_Wn1F, wid * 4, 0, d, lane);
    __syncthreads();
    build_a_frags(a_s, &g_agg[node * 256], e, jq);
    __syncthreads();
    mma_gemm_w<32>(a_s, g_Wn1F, wid * 4, 8, d, lane);
    __syncthreads();

#pragma unroll
    for (int mt = 0; mt < 4; mt++) {
        int e_lo = mt * 16 + gid;
#pragma unroll
        for (int nt = 0; nt < 4; nt++) {
            int colb = wid * 32 + nt * 8 + 2 * tig;
#pragma unroll
            for (int q = 0; q < 4; q++) {
                int er = e_lo + (q >> 1) * 8;
                int col = colb + (q & 1);
                float v = silu_f(d[mt][nt][q] + bn1_s[col]);
                a_s[afrag_idx(er, col)] = tf32f(v);
            }
        }
    }
    __syncthreads();

    zero_d(d);
    mma_gemm_w<32>(a_s, g_Wn2F, wid * 4, 0, d, lane);
#pragma unroll
    for (int mt = 0; mt < 4; mt++) {
        int row = row0 + mt * 16 + gid;
#pragma unroll
        for (int nt = 0; nt < 4; nt++) {
            int col = wid * 32 + nt * 8 + 2 * tig;
            if (row < NN) {
                float2 hv = *(const float2*)&h[row * 256 + col];
                *(float2*)&out[row * 256 + col] =
                    make_float2(d[mt][nt][0] + bn2_s[col] + hv.x,
                                d[mt][nt][1] + bn2_s[col + 1] + hv.y);
            }
            if (row + 8 < NN) {
                float2 hv = *(const float2*)&h[(row + 8) * 256 + col];
                *(float2*)&out[(row + 8) * 256 + col] =
                    make_float2(d[mt][nt][2] + bn2_s[col] + hv.x,
                                d[mt][nt][3] + bn2_s[col + 1] + hv.y);
            }
        }
    }
}

// ---------------- coord finalize ----------------
__global__ void coord_kernel(const float* __restrict__ coord, float* __restrict__ out) {
    int i = blockIdx.x * blockDim.x + threadIdx.x;
    if (i < NN) {
        float cnt = g_cnt[i];
        if (cnt < 1.0f) cnt = 1.0f;
        float inv = 1.0f / cnt;
        out[NN * 256 + i * 3]     = coord[i * 3]     + g_csum[i * 3]     * inv;
        out[NN * 256 + i * 3 + 1] = coord[i * 3 + 1] + g_csum[i * 3 + 1] * inv;
        out[NN * 256 + i * 3 + 2] = coord[i * 3 + 2] + g_csum[i * 3 + 2] * inv;
    }
}

// ---------------- launch ----------------
extern "C" void kernel_launch(void* const* d_in, const int* in_sizes, int n_in,
                              void* d_out, int out_size) {
    const float* h    = (const float*)d_in[0];
    const int*   eidx = (const int*)d_in[1];
    const float* coord = (const float*)d_in[2];
    const float* We1  = (const float*)d_in[3];
    const float* be1  = (const float*)d_in[4];
    const float* We2  = (const float*)d_in[5];
    const float* be2  = (const float*)d_in[6];
    const float* Wn1  = (const float*)d_in[7];
    const float* bn1  = (const float*)d_in[8];
    const float* Wn2  = (const float*)d_in[9];
    const float* bn2  = (const float*)d_in[10];
    const float* Wc1  = (const float*)d_in[11];
    const float* bc1  = (const float*)d_in[12];
    const float* Wc2  = (const float*)d_in[13];
    float* out = (float*)d_out;

    cudaFuncSetAttribute(gemm_ab, cudaFuncAttributeMaxDynamicSharedMemorySize,
                         AB_SMEM_BYTES);
    cudaFuncSetAttribute(edge_kernel, cudaFuncAttributeMaxDynamicSharedMemorySize,
                         EDGE_SMEM_BYTES);
    cudaFuncSetAttribute(node_kernel, cudaFuncAttributeMaxDynamicSharedMemorySize,
                         NODE_SMEM_BYTES);

    prep_kernel<<<512, 256>>>(We1, We2, Wc1, Wn1, Wn2);
    gemm_ab<<<dim3(782, 2), 256, AB_SMEM_BYTES>>>(h);
    edge_kernel<<<NE / 64, 256, EDGE_SMEM_BYTES>>>(eidx, coord, be1, be2, bc1, Wc2);
    node_kernel<<<782, 256, NODE_SMEM_BYTES>>>(h, bn1, bn2, out);
    coord_kernel<<<(NN + 255) / 256, 256>>>(coord, out);
}